// round 10
// baseline (speedup 1.0000x reference)
#include <cuda_runtime.h>
#include <cuda_bf16.h>
#include <cstdint>
#include <math.h>

#define NB   32
#define SQ   512
#define DIM  512
#define K2   1024
#define OFF  (NB * SQ * DIM)
#define SCALE 0.04419417382415922f

// ---------------------------------------------------------------------------
// Scratch (__device__ globals: allocation-free rule)
// ---------------------------------------------------------------------------
__device__ __align__(256) __nv_bfloat16 gQh[NB*SQ*DIM], gQl[NB*SQ*DIM];
__device__ __align__(256) __nv_bfloat16 gEh[NB*SQ*DIM], gEl[NB*SQ*DIM];
__device__ __align__(256) __nv_bfloat16 gEth[NB*DIM*SQ], gEtl[NB*DIM*SQ]; // E^T [d][s]
__device__ __align__(256) __nv_bfloat16 gPh[NB*SQ*SQ],  gPl[NB*SQ*SQ];   // softmax split
__device__ __align__(256) __nv_bfloat16 gCh[NB*SQ*DIM], gCl[NB*SQ*DIM];  // context split
__device__ __align__(256) __nv_bfloat16 gWh[DIM*K2],    gWl[DIM*K2];
__device__ float g_scores[NB*SQ*SQ];

// ---------------------------------------------------------------------------
// PTX helpers (plain-sm_103-safe: mma.sync / ldmatrix / cp.async)
// ---------------------------------------------------------------------------
__device__ __forceinline__ uint32_t smem_u32(const void* p) {
    uint32_t a;
    asm("{ .reg .u64 t; cvta.to.shared.u64 t, %1; cvt.u32.u64 %0, t; }" : "=r"(a) : "l"(p));
    return a;
}
__device__ __forceinline__ void cp16(uint32_t s, const void* g) {
    asm volatile("cp.async.cg.shared.global [%0], [%1], 16;" :: "r"(s), "l"(g));
}
#define CP_COMMIT() asm volatile("cp.async.commit_group;" ::: "memory")
#define CP_WAIT0()  asm volatile("cp.async.wait_group 0;" ::: "memory")

__device__ __forceinline__ void ldsm4(uint32_t* r, uint32_t addr) {
    asm volatile("ldmatrix.sync.aligned.m8n8.x4.shared.b16 {%0,%1,%2,%3}, [%4];"
        : "=r"(r[0]), "=r"(r[1]), "=r"(r[2]), "=r"(r[3]) : "r"(addr));
}
__device__ __forceinline__ void mma_bf16(float* d, const uint32_t* a, uint32_t b0, uint32_t b1) {
    asm volatile("mma.sync.aligned.m16n8k16.row.col.f32.bf16.bf16.f32 "
        "{%0,%1,%2,%3}, {%4,%5,%6,%7}, {%8,%9}, {%0,%1,%2,%3};"
        : "+f"(d[0]), "+f"(d[1]), "+f"(d[2]), "+f"(d[3])
        : "r"(a[0]), "r"(a[1]), "r"(a[2]), "r"(a[3]), "r"(b0), "r"(b1));
}

// SW128 swizzle for 128B rows (64 bf16/row), tile = 128 rows x 128B = 16KB
__device__ __forceinline__ uint32_t sw128(int r, int c16) {
    return (uint32_t)(r * 128 + (((c16) ^ (r & 7)) << 4));
}

// ---------------------------------------------------------------------------
// Conversion kernels
// ---------------------------------------------------------------------------
__device__ __forceinline__ void split4(float4 v, __nv_bfloat16* dh, __nv_bfloat16* dl) {
    union { __nv_bfloat16 h[4]; uint2 u; } H, L;
    float f[4] = {v.x, v.y, v.z, v.w};
    #pragma unroll
    for (int j = 0; j < 4; j++) {
        __nv_bfloat16 h = __float2bfloat16(f[j]);
        H.h[j] = h;
        L.h[j] = __float2bfloat16(f[j] - __bfloat162float(h));
    }
    *(uint2*)dh = H.u;
    *(uint2*)dl = L.u;
}

__global__ __launch_bounds__(256) void split_q_kernel(const float* __restrict__ Q)
{
    size_t i = ((size_t)blockIdx.x * 256 + threadIdx.x) * 4;
    split4(*(const float4*)(Q + i), gQh + i, gQl + i);
}

__global__ __launch_bounds__(256) void split_w_kernel(const float* __restrict__ W)
{
    size_t i = ((size_t)blockIdx.x * 256 + threadIdx.x) * 4;
    split4(*(const float4*)(W + i), gWh + i, gWl + i);
}

// E -> row-major split (gEh/gEl) AND transposed split (gEth/gEtl), one read of E
__global__ __launch_bounds__(256) void split_transpose_e_kernel(const float* __restrict__ E)
{
    __shared__ float t[32][33];
    const int b = blockIdx.z;
    const int tx = threadIdx.x, ty = threadIdx.y;       // block (32, 8)
    const int x = blockIdx.x * 32 + tx;                 // d (read)
    const int y0 = blockIdx.y * 32;                     // s base
    const size_t base = (size_t)b * SQ * DIM;
    const float* Eb = E + base;
    #pragma unroll
    for (int j = 0; j < 32; j += 8) {
        float f = Eb[(size_t)(y0 + ty + j) * DIM + x];
        t[ty + j][tx] = f;
        __nv_bfloat16 h = __float2bfloat16(f);
        size_t o = base + (size_t)(y0 + ty + j) * DIM + x;
        gEh[o] = h;
        gEl[o] = __float2bfloat16(f - __bfloat162float(h));
    }
    __syncthreads();
    const int s = y0 + tx;
    const int d0 = blockIdx.x * 32;
    #pragma unroll
    for (int j = 0; j < 32; j += 8) {
        float f = t[tx][ty + j];
        __nv_bfloat16 h = __float2bfloat16(f);
        size_t o = base + (size_t)(d0 + ty + j) * SQ + s;
        gEth[o] = h;
        gEtl[o] = __float2bfloat16(f - __bfloat162float(h));
    }
}

// ---------------------------------------------------------------------------
// Softmax: g_scores -> weights (fp32, d_out+OFF) + bf16 split P
// ---------------------------------------------------------------------------
__global__ __launch_bounds__(256) void softmax_kernel(float* __restrict__ wout)
{
    __shared__ float redm[8], reds[8];
    const int row = blockIdx.x;
    const float* s = g_scores + (size_t)row * SQ;
    float* w = wout + (size_t)row * SQ;
    const int tid = threadIdx.x;

    float v0 = s[tid], v1 = s[tid + 256];
    float m = fmaxf(v0, v1);
    #pragma unroll
    for (int o = 16; o > 0; o >>= 1) m = fmaxf(m, __shfl_xor_sync(0xffffffffu, m, o));
    if ((tid & 31) == 0) redm[tid >> 5] = m;
    __syncthreads();
    if (tid < 32) {
        float t = (tid < 8) ? redm[tid] : -INFINITY;
        #pragma unroll
        for (int o = 4; o > 0; o >>= 1) t = fmaxf(t, __shfl_xor_sync(0xffffffffu, t, o));
        if (tid == 0) redm[0] = t;
    }
    __syncthreads();
    m = redm[0];
    float e0 = __expf(v0 - m), e1 = __expf(v1 - m);
    float sum = e0 + e1;
    #pragma unroll
    for (int o = 16; o > 0; o >>= 1) sum += __shfl_xor_sync(0xffffffffu, sum, o);
    if ((tid & 31) == 0) reds[tid >> 5] = sum;
    __syncthreads();
    if (tid < 32) {
        float t = (tid < 8) ? reds[tid] : 0.0f;
        #pragma unroll
        for (int o = 4; o > 0; o >>= 1) t += __shfl_xor_sync(0xffffffffu, t, o);
        if (tid == 0) reds[0] = t;
    }
    __syncthreads();
    float inv = __frcp_rn(reds[0]);
    float w0 = e0 * inv, w1 = e1 * inv;
    w[tid] = w0; w[tid + 256] = w1;
    size_t o = (size_t)row * SQ;
    __nv_bfloat16 h0 = __float2bfloat16(w0);
    __nv_bfloat16 h1 = __float2bfloat16(w1);
    gPh[o + tid] = h0;       gPl[o + tid]       = __float2bfloat16(w0 - __bfloat162float(h0));
    gPh[o + tid + 256] = h1; gPl[o + tid + 256] = __float2bfloat16(w1 - __bfloat162float(h1));
}

// ---------------------------------------------------------------------------
// mma.sync bf16-split GEMM (terms as extra K chunks: Ah*Bh + Al*Bh + Ah*Bl),
// 128x128 CTA tile, BK=64, 2-stage cp.async double buffer, 4 warps (2x2),
// 64x64 warp tile, __launch_bounds__(128,3) -> 3 CTAs/SM to decorrelate
// barrier phases across CTAs and keep the tensor pipe fed.
// MODE 0: scores  S = Q @ E^T * scale          (batched, K=512)
// MODE 1: context C = P @ Et^T                 (batched, K=512) -> bf16 split
// MODE 2: final   O = tanh([Q|C] @ W^T + b)*mk (flat M=16384, K=1024)
// ---------------------------------------------------------------------------
#define STG 32768                       // per-stage: A 16KB + B 16KB
#define GEMM_SMEM (2 * STG)

template <int MODE>
__global__ __launch_bounds__(128, 3) void gemm_kernel(
    const float* __restrict__ bias, const float* __restrict__ mask,
    float* __restrict__ out)
{
    extern __shared__ __align__(128) char sm[];
    const uint32_t sbase = smem_u32(sm);
    const int tid = threadIdx.x;
    const int lane = tid & 31, wid = tid >> 5;
    const int wm = wid & 1, wn = wid >> 1;           // 2 x 2 warps
    const int m0 = blockIdx.y * 128, n0 = blockIdx.x * 128;

    constexpr int K   = (MODE == 2) ? K2 : 512;
    constexpr int KC  = K / 64;                      // chunks per term
    constexpr int NC  = 3 * KC;
    constexpr int LDA = (MODE == 1) ? SQ : DIM;
    constexpr int LDB = (MODE == 2) ? K2 : ((MODE == 1) ? SQ : DIM);

    size_t offA = 0, offB = 0;
    if constexpr (MODE == 0) { offA = (size_t)blockIdx.z * SQ * DIM; offB = offA; }
    if constexpr (MODE == 1) { offA = (size_t)blockIdx.z * SQ * SQ;
                               offB = (size_t)blockIdx.z * DIM * SQ; }

    // ---- load-side: 128 threads cover rows {r0 + 16*it}, fixed 16B col c16
    const int r0  = tid >> 3;            // 0..15
    const int c16 = tid & 7;
    const uint32_t swb = sw128(r0, c16); // +16 rows -> +2048 B (XOR bits invariant)

    auto load_chunk = [&](int q, int st) {
        const int term = q / KC;
        const int kk   = (q - term * KC) * 64;
        const __nv_bfloat16 *A_, *B_;
        int ka = kk;
        if constexpr (MODE == 0) {
            A_ = ((term == 1) ? gQl : gQh) + offA;
            B_ = ((term == 2) ? gEl : gEh) + offB;
        } else if constexpr (MODE == 1) {
            A_ = ((term == 1) ? gPl  : gPh)  + offA;
            B_ = ((term == 2) ? gEtl : gEth) + offB;
        } else {
            if (kk < 512) { A_ = (term == 1) ? gQl : gQh; }
            else          { A_ = (term == 1) ? gCl : gCh; ka = kk - 512; }
            B_ = (term == 2) ? gWl : gWh;
        }
        const __nv_bfloat16* ga = A_ + (size_t)(m0 + r0) * LDA + ka + c16 * 8;
        const __nv_bfloat16* gb = B_ + (size_t)(n0 + r0) * LDB + kk + c16 * 8;
        const uint32_t sA = sbase + (uint32_t)st * STG + swb;
        const uint32_t sB = sA + 16384;
        #pragma unroll
        for (int it = 0; it < 8; it++) {
            cp16(sA + it * 2048, ga + (size_t)it * 16 * LDA);
            cp16(sB + it * 2048, gb + (size_t)it * 16 * LDB);
        }
        CP_COMMIT();
    };

    // ---- mma-side hoisted base addresses
    const int lrow = lane & 15, lch = lane >> 4;
    uint32_t aB[4], bB[4];
    #pragma unroll
    for (int ks = 0; ks < 4; ks++) {
        aB[ks] = sbase + sw128(wm * 64 + lrow, ks * 2 + lch);
        bB[ks] = sbase + 16384 + sw128(wn * 64 + lrow, ks * 2 + lch);
    }

    float acc[4][8][4];
    #pragma unroll
    for (int i = 0; i < 4; i++)
        #pragma unroll
        for (int j = 0; j < 8; j++)
            #pragma unroll
            for (int v = 0; v < 4; v++) acc[i][j][v] = 0.0f;

    load_chunk(0, 0);

    for (int c = 0; c < NC; c++) {
        CP_WAIT0();                       // load c landed (overlapped compute c-1)
        __syncthreads();                  // all warps done reading stage (c+1)&1
        if (c + 1 < NC) load_chunk(c + 1, (c + 1) & 1);   // overlaps compute c

        const uint32_t soff = (uint32_t)(c & 1) * STG;
        #pragma unroll
        for (int ks = 0; ks < 4; ks++) {
            uint32_t a[4][4], b[4][4];
            const uint32_t ab = aB[ks] + soff, bb = bB[ks] + soff;
            #pragma unroll
            for (int im = 0; im < 4; im++) ldsm4(a[im], ab + im * 2048);
            #pragma unroll
            for (int jn = 0; jn < 4; jn++) ldsm4(b[jn], bb + jn * 2048);
            #pragma unroll
            for (int im = 0; im < 4; im++)
                #pragma unroll
                for (int j = 0; j < 8; j++)
                    mma_bf16(acc[im][j], a[im], b[j>>1][j&1], b[j>>1][(j&1)+2]);
        }
    }

    // ---------------- epilogue ----------------
    const int gid = lane >> 2, tig = lane & 3;
    #pragma unroll
    for (int im = 0; im < 4; im++) {
        const int m = m0 + wm*64 + im*16 + gid;       // rows m, m+8
        float mk0 = 0.f, mk1 = 0.f;
        if constexpr (MODE == 2) { mk0 = mask[m]; mk1 = mask[m + 8]; }
        #pragma unroll
        for (int j = 0; j < 8; j++) {
            const int n = n0 + wn*64 + j*8 + tig*2;
            const float* A4 = acc[im][j];
            if constexpr (MODE == 0) {
                float* C = g_scores + (size_t)blockIdx.z * SQ * SQ;
                *(float2*)(C + (size_t)m * SQ + n)     = {A4[0]*SCALE, A4[1]*SCALE};
                *(float2*)(C + (size_t)(m+8) * SQ + n) = {A4[2]*SCALE, A4[3]*SCALE};
            } else if constexpr (MODE == 1) {
                const size_t base = (size_t)blockIdx.z * SQ * DIM;
                #pragma unroll
                for (int rr = 0; rr < 2; rr++) {
                    const size_t o = base + (size_t)(m + rr*8) * DIM + n;
                    float f0 = A4[rr*2], f1 = A4[rr*2+1];
                    union { __nv_bfloat16 h[2]; uint32_t u; } H, L;
                    __nv_bfloat16 h0 = __float2bfloat16(f0);
                    __nv_bfloat16 h1 = __float2bfloat16(f1);
                    H.h[0] = h0; H.h[1] = h1;
                    L.h[0] = __float2bfloat16(f0 - __bfloat162float(h0));
                    L.h[1] = __float2bfloat16(f1 - __bfloat162float(h1));
                    *(uint32_t*)(gCh + o) = H.u;
                    *(uint32_t*)(gCl + o) = L.u;
                }
            } else {
                const float b0 = bias[n], b1 = bias[n + 1];
                *(float2*)(out + (size_t)m * DIM + n) =
                    {tanhf(A4[0] + b0) * mk0, tanhf(A4[1] + b1) * mk0};
                *(float2*)(out + (size_t)(m+8) * DIM + n) =
                    {tanhf(A4[2] + b0) * mk1, tanhf(A4[3] + b1) * mk1};
            }
        }
    }
}

// ---------------------------------------------------------------------------
extern "C" void kernel_launch(void* const* d_in, const int* in_sizes, int n_in,
                              void* d_out, int out_size)
{
    const float* Q    = (const float*)d_in[0];  // (32, 512, 512)
    const float* E    = (const float*)d_in[1];  // (32, 512, 512)
    const float* mask = (const float*)d_in[2];  // (32, 512, 1)
    const float* W    = (const float*)d_in[3];  // (512, 1024)
    const float* bias = (const float*)d_in[4];  // (512,)
    float* out  = (float*)d_out;
    float* wout = out + OFF;

    static bool attr_done = false;
    if (!attr_done) {
        cudaFuncSetAttribute(gemm_kernel<0>, cudaFuncAttributeMaxDynamicSharedMemorySize, GEMM_SMEM);
        cudaFuncSetAttribute(gemm_kernel<1>, cudaFuncAttributeMaxDynamicSharedMemorySize, GEMM_SMEM);
        cudaFuncSetAttribute(gemm_kernel<2>, cudaFuncAttributeMaxDynamicSharedMemorySize, GEMM_SMEM);
        attr_done = true;
    }

    split_q_kernel          <<<8192, 256>>>(Q);
    split_w_kernel          <<<512, 256>>>(W);
    split_transpose_e_kernel<<<dim3(16, 16, 32), dim3(32, 8)>>>(E);

    gemm_kernel<0><<<dim3(4, 4, 32),  128, GEMM_SMEM>>>(nullptr, nullptr, nullptr);
    softmax_kernel<<<NB * SQ, 256>>>(wout);
    gemm_kernel<1><<<dim3(4, 4, 32),  128, GEMM_SMEM>>>(nullptr, nullptr, nullptr);
    gemm_kernel<2><<<dim3(4, 128, 1), 128, GEMM_SMEM>>>(bias, mask, out);
}

// round 11
// speedup vs baseline: 1.0781x; 1.0781x over previous
#include <cuda_runtime.h>
#include <cuda_bf16.h>
#include <cstdint>
#include <math.h>

#define NB   32
#define SQ   512
#define DIM  512
#define K2   1024
#define OFF  (NB * SQ * DIM)
#define SCALE 0.04419417382415922f

// ---------------------------------------------------------------------------
// Scratch (__device__ globals: allocation-free rule)
// ---------------------------------------------------------------------------
__device__ __align__(256) __nv_bfloat16 gQh[NB*SQ*DIM], gQl[NB*SQ*DIM];
__device__ __align__(256) __nv_bfloat16 gEh[NB*SQ*DIM], gEl[NB*SQ*DIM];
__device__ __align__(256) __nv_bfloat16 gEth[NB*DIM*SQ], gEtl[NB*DIM*SQ]; // E^T [d][s]
__device__ __align__(256) __nv_bfloat16 gPh[NB*SQ*SQ],  gPl[NB*SQ*SQ];   // softmax split
__device__ __align__(256) __nv_bfloat16 gCh[NB*SQ*DIM], gCl[NB*SQ*DIM];  // context split
__device__ __align__(256) __nv_bfloat16 gWh[DIM*K2],    gWl[DIM*K2];
__device__ float g_scores[NB*SQ*SQ];

// ---------------------------------------------------------------------------
// PTX helpers (plain-sm_103-safe: mma.sync / ldmatrix / cp.async)
// ---------------------------------------------------------------------------
__device__ __forceinline__ uint32_t smem_u32(const void* p) {
    uint32_t a;
    asm("{ .reg .u64 t; cvta.to.shared.u64 t, %1; cvt.u32.u64 %0, t; }" : "=r"(a) : "l"(p));
    return a;
}
__device__ __forceinline__ void cp16(uint32_t s, const void* g) {
    asm volatile("cp.async.cg.shared.global [%0], [%1], 16;" :: "r"(s), "l"(g));
}
#define CP_COMMIT() asm volatile("cp.async.commit_group;" ::: "memory")
#define CP_WAIT1()  asm volatile("cp.async.wait_group 1;" ::: "memory")

__device__ __forceinline__ void ldsm4(uint32_t* r, uint32_t addr) {
    asm volatile("ldmatrix.sync.aligned.m8n8.x4.shared.b16 {%0,%1,%2,%3}, [%4];"
        : "=r"(r[0]), "=r"(r[1]), "=r"(r[2]), "=r"(r[3]) : "r"(addr));
}
__device__ __forceinline__ void mma_bf16(float* d, const uint32_t* a, uint32_t b0, uint32_t b1) {
    asm volatile("mma.sync.aligned.m16n8k16.row.col.f32.bf16.bf16.f32 "
        "{%0,%1,%2,%3}, {%4,%5,%6,%7}, {%8,%9}, {%0,%1,%2,%3};"
        : "+f"(d[0]), "+f"(d[1]), "+f"(d[2]), "+f"(d[3])
        : "r"(a[0]), "r"(a[1]), "r"(a[2]), "r"(a[3]), "r"(b0), "r"(b1));
}
__device__ __forceinline__ float tanh_fast(float x) {
    float y;
    asm("tanh.approx.f32 %0, %1;" : "=f"(y) : "f"(x));
    return y;
}

// SW128 swizzle for 128B rows (64 bf16/row), tile = 128 rows x 128B = 16KB
__device__ __forceinline__ uint32_t sw128(int r, int c16) {
    return (uint32_t)(r * 128 + (((c16) ^ (r & 7)) << 4));
}

// ---------------------------------------------------------------------------
// Conversion kernels
// ---------------------------------------------------------------------------
__device__ __forceinline__ void split4(float4 v, __nv_bfloat16* dh, __nv_bfloat16* dl) {
    union { __nv_bfloat16 h[4]; uint2 u; } H, L;
    float f[4] = {v.x, v.y, v.z, v.w};
    #pragma unroll
    for (int j = 0; j < 4; j++) {
        __nv_bfloat16 h = __float2bfloat16(f[j]);
        H.h[j] = h;
        L.h[j] = __float2bfloat16(f[j] - __bfloat162float(h));
    }
    *(uint2*)dh = H.u;
    *(uint2*)dl = L.u;
}

__global__ __launch_bounds__(256) void split_q_kernel(const float* __restrict__ Q)
{
    size_t i = ((size_t)blockIdx.x * 256 + threadIdx.x) * 4;
    split4(*(const float4*)(Q + i), gQh + i, gQl + i);
}

__global__ __launch_bounds__(256) void split_w_kernel(const float* __restrict__ W)
{
    size_t i = ((size_t)blockIdx.x * 256 + threadIdx.x) * 4;
    split4(*(const float4*)(W + i), gWh + i, gWl + i);
}

// E -> row-major split (gEh/gEl) AND transposed split (gEth/gEtl), one read of E
__global__ __launch_bounds__(256) void split_transpose_e_kernel(const float* __restrict__ E)
{
    __shared__ float t[32][33];
    const int b = blockIdx.z;
    const int tx = threadIdx.x, ty = threadIdx.y;       // block (32, 8)
    const int x = blockIdx.x * 32 + tx;                 // d (read)
    const int y0 = blockIdx.y * 32;                     // s base
    const size_t base = (size_t)b * SQ * DIM;
    const float* Eb = E + base;
    #pragma unroll
    for (int j = 0; j < 32; j += 8) {
        float f = Eb[(size_t)(y0 + ty + j) * DIM + x];
        t[ty + j][tx] = f;
        __nv_bfloat16 h = __float2bfloat16(f);
        size_t o = base + (size_t)(y0 + ty + j) * DIM + x;
        gEh[o] = h;
        gEl[o] = __float2bfloat16(f - __bfloat162float(h));
    }
    __syncthreads();
    const int s = y0 + tx;
    const int d0 = blockIdx.x * 32;
    #pragma unroll
    for (int j = 0; j < 32; j += 8) {
        float f = t[tx][ty + j];
        __nv_bfloat16 h = __float2bfloat16(f);
        size_t o = base + (size_t)(d0 + ty + j) * SQ + s;
        gEth[o] = h;
        gEtl[o] = __float2bfloat16(f - __bfloat162float(h));
    }
}

// ---------------------------------------------------------------------------
// Softmax: g_scores -> weights (fp32, d_out+OFF) + bf16 split P
// ---------------------------------------------------------------------------
__global__ __launch_bounds__(256) void softmax_kernel(float* __restrict__ wout)
{
    __shared__ float redm[8], reds[8];
    const int row = blockIdx.x;
    const float* s = g_scores + (size_t)row * SQ;
    float* w = wout + (size_t)row * SQ;
    const int tid = threadIdx.x;

    float v0 = s[tid], v1 = s[tid + 256];
    float m = fmaxf(v0, v1);
    #pragma unroll
    for (int o = 16; o > 0; o >>= 1) m = fmaxf(m, __shfl_xor_sync(0xffffffffu, m, o));
    if ((tid & 31) == 0) redm[tid >> 5] = m;
    __syncthreads();
    if (tid < 32) {
        float t = (tid < 8) ? redm[tid] : -INFINITY;
        #pragma unroll
        for (int o = 4; o > 0; o >>= 1) t = fmaxf(t, __shfl_xor_sync(0xffffffffu, t, o));
        if (tid == 0) redm[0] = t;
    }
    __syncthreads();
    m = redm[0];
    float e0 = __expf(v0 - m), e1 = __expf(v1 - m);
    float sum = e0 + e1;
    #pragma unroll
    for (int o = 16; o > 0; o >>= 1) sum += __shfl_xor_sync(0xffffffffu, sum, o);
    if ((tid & 31) == 0) reds[tid >> 5] = sum;
    __syncthreads();
    if (tid < 32) {
        float t = (tid < 8) ? reds[tid] : 0.0f;
        #pragma unroll
        for (int o = 4; o > 0; o >>= 1) t += __shfl_xor_sync(0xffffffffu, t, o);
        if (tid == 0) reds[0] = t;
    }
    __syncthreads();
    float inv = __frcp_rn(reds[0]);
    float w0 = e0 * inv, w1 = e1 * inv;
    w[tid] = w0; w[tid + 256] = w1;
    size_t o = (size_t)row * SQ;
    __nv_bfloat16 h0 = __float2bfloat16(w0);
    __nv_bfloat16 h1 = __float2bfloat16(w1);
    gPh[o + tid] = h0;       gPl[o + tid]       = __float2bfloat16(w0 - __bfloat162float(h0));
    gPh[o + tid + 256] = h1; gPl[o + tid + 256] = __float2bfloat16(w1 - __bfloat162float(h1));
}

// ---------------------------------------------------------------------------
// mma.sync bf16-split GEMM (terms as extra K chunks: Ah*Bh + Al*Bh + Ah*Bl),
// 128x128 CTA tile, BK=64, 3-stage cp.async, 4 warps (2x2), 64x64 warp tile.
// Fragments software-pipelined: ldsm of k-step ks+1 issues before MMAs of ks,
// hiding LDS latency under tensor-pipe issue.
// MODE 0: scores  S = Q @ E^T * scale          (batched, K=512)
// MODE 1: context C = P @ Et^T                 (batched, K=512) -> bf16 split
// MODE 2: final   O = tanh([Q|C] @ W^T + b)*mk (flat M=16384, K=1024)
// ---------------------------------------------------------------------------
#define STG 32768                       // per-stage: A 16KB + B 16KB
#define GEMM_SMEM (3 * STG)

template <int MODE>
__global__ __launch_bounds__(128, 2) void gemm_kernel(
    const float* __restrict__ bias, const float* __restrict__ mask,
    float* __restrict__ out)
{
    extern __shared__ __align__(128) char sm[];
    const uint32_t sbase = smem_u32(sm);
    const int tid = threadIdx.x;
    const int lane = tid & 31, wid = tid >> 5;
    const int wm = wid & 1, wn = wid >> 1;           // 2 x 2 warps
    const int m0 = blockIdx.y * 128, n0 = blockIdx.x * 128;

    constexpr int K   = (MODE == 2) ? K2 : 512;
    constexpr int KC  = K / 64;                      // chunks per term
    constexpr int NC  = 3 * KC;
    constexpr int LDA = (MODE == 1) ? SQ : DIM;
    constexpr int LDB = (MODE == 2) ? K2 : ((MODE == 1) ? SQ : DIM);

    size_t offA = 0, offB = 0;
    if constexpr (MODE == 0) { offA = (size_t)blockIdx.z * SQ * DIM; offB = offA; }
    if constexpr (MODE == 1) { offA = (size_t)blockIdx.z * SQ * SQ;
                               offB = (size_t)blockIdx.z * DIM * SQ; }

    // ---- load-side: 128 threads cover rows {r0 + 16*it}, fixed 16B col c16
    const int r0  = tid >> 3;            // 0..15
    const int c16 = tid & 7;
    const uint32_t swb = sw128(r0, c16);

    auto load_chunk = [&](int q, int st) {
        const int term = q / KC;
        const int kk   = (q - term * KC) * 64;
        const __nv_bfloat16 *A_, *B_;
        int ka = kk;
        if constexpr (MODE == 0) {
            A_ = ((term == 1) ? gQl : gQh) + offA;
            B_ = ((term == 2) ? gEl : gEh) + offB;
        } else if constexpr (MODE == 1) {
            A_ = ((term == 1) ? gPl  : gPh)  + offA;
            B_ = ((term == 2) ? gEtl : gEth) + offB;
        } else {
            if (kk < 512) { A_ = (term == 1) ? gQl : gQh; }
            else          { A_ = (term == 1) ? gCl : gCh; ka = kk - 512; }
            B_ = (term == 2) ? gWl : gWh;
        }
        const __nv_bfloat16* ga = A_ + (size_t)(m0 + r0) * LDA + ka + c16 * 8;
        const __nv_bfloat16* gb = B_ + (size_t)(n0 + r0) * LDB + kk + c16 * 8;
        const uint32_t sA = sbase + (uint32_t)st * STG + swb;
        const uint32_t sB = sA + 16384;
        #pragma unroll
        for (int it = 0; it < 8; it++) {
            cp16(sA + it * 2048, ga + (size_t)it * 16 * LDA);
            cp16(sB + it * 2048, gb + (size_t)it * 16 * LDB);
        }
        CP_COMMIT();
    };

    // ---- mma-side hoisted base addresses
    const int lrow = lane & 15, lch = lane >> 4;
    uint32_t aB[4], bB[4];
    #pragma unroll
    for (int ks = 0; ks < 4; ks++) {
        aB[ks] = sbase + sw128(wm * 64 + lrow, ks * 2 + lch);
        bB[ks] = sbase + 16384 + sw128(wn * 64 + lrow, ks * 2 + lch);
    }

    float acc[4][8][4];
    #pragma unroll
    for (int i = 0; i < 4; i++)
        #pragma unroll
        for (int j = 0; j < 8; j++)
            #pragma unroll
            for (int v = 0; v < 4; v++) acc[i][j][v] = 0.0f;

    load_chunk(0, 0);
    load_chunk(1, 1);

    for (int c = 0; c < NC; c++) {
        CP_WAIT1();
        __syncthreads();
        if (c + 2 < NC) load_chunk(c + 2, (c + 2) % 3);
        else            CP_COMMIT();

        const uint32_t soff = (uint32_t)(c % 3) * STG;

        // fragment double-buffer: preload ks=0, then ldsm ks+1 before mma ks
        uint32_t a[2][4][4], b[2][4][4];
        #pragma unroll
        for (int im = 0; im < 4; im++) ldsm4(a[0][im], aB[0] + soff + im * 2048);
        #pragma unroll
        for (int jn = 0; jn < 4; jn++) ldsm4(b[0][jn], bB[0] + soff + jn * 2048);

        #pragma unroll
        for (int ks = 0; ks < 4; ks++) {
            const int cur = ks & 1, nxt = cur ^ 1;
            if (ks < 3) {
                const uint32_t ab = aB[ks + 1] + soff, bb = bB[ks + 1] + soff;
                #pragma unroll
                for (int im = 0; im < 4; im++) ldsm4(a[nxt][im], ab + im * 2048);
                #pragma unroll
                for (int jn = 0; jn < 4; jn++) ldsm4(b[nxt][jn], bb + jn * 2048);
            }
            #pragma unroll
            for (int im = 0; im < 4; im++)
                #pragma unroll
                for (int j = 0; j < 8; j++)
                    mma_bf16(acc[im][j], a[cur][im], b[cur][j>>1][j&1], b[cur][j>>1][(j&1)+2]);
        }
        __syncthreads();
    }

    // ---------------- epilogue ----------------
    const int gid = lane >> 2, tig = lane & 3;
    #pragma unroll
    for (int im = 0; im < 4; im++) {
        const int m = m0 + wm*64 + im*16 + gid;       // rows m, m+8
        float mk0 = 0.f, mk1 = 0.f;
        if constexpr (MODE == 2) { mk0 = mask[m]; mk1 = mask[m + 8]; }
        #pragma unroll
        for (int j = 0; j < 8; j++) {
            const int n = n0 + wn*64 + j*8 + tig*2;
            const float* A4 = acc[im][j];
            if constexpr (MODE == 0) {
                float* C = g_scores + (size_t)blockIdx.z * SQ * SQ;
                *(float2*)(C + (size_t)m * SQ + n)     = {A4[0]*SCALE, A4[1]*SCALE};
                *(float2*)(C + (size_t)(m+8) * SQ + n) = {A4[2]*SCALE, A4[3]*SCALE};
            } else if constexpr (MODE == 1) {
                const size_t base = (size_t)blockIdx.z * SQ * DIM;
                #pragma unroll
                for (int rr = 0; rr < 2; rr++) {
                    const size_t o = base + (size_t)(m + rr*8) * DIM + n;
                    float f0 = A4[rr*2], f1 = A4[rr*2+1];
                    union { __nv_bfloat16 h[2]; uint32_t u; } H, L;
                    __nv_bfloat16 h0 = __float2bfloat16(f0);
                    __nv_bfloat16 h1 = __float2bfloat16(f1);
                    H.h[0] = h0; H.h[1] = h1;
                    L.h[0] = __float2bfloat16(f0 - __bfloat162float(h0));
                    L.h[1] = __float2bfloat16(f1 - __bfloat162float(h1));
                    *(uint32_t*)(gCh + o) = H.u;
                    *(uint32_t*)(gCl + o) = L.u;
                }
            } else {
                const float b0 = bias[n], b1 = bias[n + 1];
                *(float2*)(out + (size_t)m * DIM + n) =
                    {tanh_fast(A4[0] + b0) * mk0, tanh_fast(A4[1] + b1) * mk0};
                *(float2*)(out + (size_t)(m+8) * DIM + n) =
                    {tanh_fast(A4[2] + b0) * mk1, tanh_fast(A4[3] + b1) * mk1};
            }
        }
    }
}

// ---------------------------------------------------------------------------
extern "C" void kernel_launch(void* const* d_in, const int* in_sizes, int n_in,
                              void* d_out, int out_size)
{
    const float* Q    = (const float*)d_in[0];  // (32, 512, 512)
    const float* E    = (const float*)d_in[1];  // (32, 512, 512)
    const float* mask = (const float*)d_in[2];  // (32, 512, 1)
    const float* W    = (const float*)d_in[3];  // (512, 1024)
    const float* bias = (const float*)d_in[4];  // (512,)
    float* out  = (float*)d_out;
    float* wout = out + OFF;

    static bool attr_done = false;
    if (!attr_done) {
        cudaFuncSetAttribute(gemm_kernel<0>, cudaFuncAttributeMaxDynamicSharedMemorySize, GEMM_SMEM);
        cudaFuncSetAttribute(gemm_kernel<1>, cudaFuncAttributeMaxDynamicSharedMemorySize, GEMM_SMEM);
        cudaFuncSetAttribute(gemm_kernel<2>, cudaFuncAttributeMaxDynamicSharedMemorySize, GEMM_SMEM);
        attr_done = true;
    }

    split_q_kernel          <<<8192, 256>>>(Q);
    split_w_kernel          <<<512, 256>>>(W);
    split_transpose_e_kernel<<<dim3(16, 16, 32), dim3(32, 8)>>>(E);

    gemm_kernel<0><<<dim3(4, 4, 32),  128, GEMM_SMEM>>>(nullptr, nullptr, nullptr);
    softmax_kernel<<<NB * SQ, 256>>>(wout);
    gemm_kernel<1><<<dim3(4, 4, 32),  128, GEMM_SMEM>>>(nullptr, nullptr, nullptr);
    gemm_kernel<2><<<dim3(4, 128, 1), 128, GEMM_SMEM>>>(bias, mask, out);
}